// round 9
// baseline (speedup 1.0000x reference)
#include <cuda_runtime.h>
#include <math.h>

#define NMAX 20000
#define U 32
#define RR 64

// Scratch (allocation-free rule: __device__ globals)
// acc layout: [n][lane(32)][12 comps padded]  (comps 0..9 used), 16B-aligned per lane
__device__ __align__(16) float g_acc[(size_t)NMAX * 384];
__device__ float g_zws[(size_t)NMAX * U];     // Z[n] @ Wemb2[:32,:]
__device__ float g_zwd[(size_t)NMAX * U];     // Z[n] @ Wemb2[32:,:]

// ---- packed fp32x2 helpers (Blackwell FFMA2) -------------------------------
__device__ __forceinline__ unsigned long long pk2(float x, float y) {
    unsigned long long r;
    asm("mov.b64 %0, {%1, %2};" : "=l"(r) : "f"(x), "f"(y));
    return r;
}
__device__ __forceinline__ unsigned long long fma2(unsigned long long a,
                                                   unsigned long long b,
                                                   unsigned long long c) {
    unsigned long long d;
    asm("fma.rn.f32x2 %0, %1, %2, %3;" : "=l"(d) : "l"(a), "l"(b), "l"(c));
    return d;
}
__device__ __forceinline__ void upk2(unsigned long long v, float& x, float& y) {
    asm("mov.b64 {%0, %1}, %2;" : "=f"(x), "=f"(y) : "l"(v));
}

// ---------------------------------------------------------------------------
// Kernel 1: zero accumulator (flat float4) + precompute ZWs/ZWd per node.
// ---------------------------------------------------------------------------
__global__ __launch_bounds__(256) void prep_kernel(
    const int* __restrict__ node_type,
    const float* __restrict__ emb_table,
    const float* __restrict__ Wemb2, int N)
{
    int t = threadIdx.x, lane = t & 31, w = t >> 5;
    int idx = blockIdx.x * 256 + t;
    int stride = gridDim.x * 256;

    float4* accv = (float4*)g_acc;
    int tot4 = N * 96;
    float4 z4 = make_float4(0.f, 0.f, 0.f, 0.f);
    for (int i = idx; i < tot4; i += stride) accv[i] = z4;

    int n = blockIdx.x * 8 + w;
    if (n >= N) return;

    float z = emb_table[node_type[n] * U + lane];
    float zs = 0.0f, zd = 0.0f;
    #pragma unroll
    for (int k = 0; k < 32; k++) {
        float zk = __shfl_sync(0xffffffffu, z, k);
        zs = fmaf(zk, Wemb2[k * U + lane], zs);
        zd = fmaf(zk, Wemb2[(k + 32) * U + lane], zd);
    }
    g_zws[(size_t)n * U + lane] = zs;
    g_zwd[(size_t)n * U + lane] = zd;
}

// ---------------------------------------------------------------------------
// Kernel 2: fused edge stage. One warp per 4 edges, FFMA2 GEMV,
// software-pipelined edge_attr staging, hoisted indirect loads,
// vectorized red.global scatter (v4+v4+v2).
// ---------------------------------------------------------------------------
__global__ __launch_bounds__(256, 2) void edge_kernel(
    const float* __restrict__ edge_attr, const float* __restrict__ bond_dist,
    const float* __restrict__ bond_vec, const int* __restrict__ src,
    const int* __restrict__ dst,
    const float* __restrict__ Wd1, const float* __restrict__ bd1,
    const float* __restrict__ Wd2, const float* __restrict__ bd2,
    const float* __restrict__ Wd3, const float* __restrict__ bd3,
    const float* __restrict__ bemb2,
    const float* __restrict__ Wemb3, const float* __restrict__ bemb3,
    float* __restrict__ edge_feat_out, int E)
{
    __shared__ float sW1[RR * U], sW2[RR * U], sW3[RR * U], sWe3[RR * U];
    __shared__ __align__(16) float sEA[8][RR][6];  // [warp][r][edge0..3,pad2]

    int t = threadIdx.x;
    for (int i = t; i < RR * U; i += 256) {
        sW1[i] = Wd1[i]; sW2[i] = Wd2[i]; sW3[i] = Wd3[i]; sWe3[i] = Wemb3[i];
    }
    __syncthreads();

    int lane = t & 31, w = t >> 5;
    float b1 = bd1[lane], b2 = bd2[lane], b3 = bd3[lane];
    float be3 = bemb3[lane], be2 = bemb2[lane];

    int g0 = blockIdx.x * 8 + w;
    int gstride = gridDim.x * 8;
    int ngroups = (E + 3) >> 2;

    // prologue: prefetch first group's edge_attr
    float pa0[4], pa1[4];
    if (g0 < ngroups) {
        #pragma unroll
        for (int ee = 0; ee < 4; ee++) {
            int e = g0 * 4 + ee;
            pa0[ee] = (e < E) ? edge_attr[(size_t)e * RR + lane] : 0.f;
            pa1[ee] = (e < E) ? edge_attr[(size_t)e * RR + lane + 32] : 0.f;
        }
    }

    for (int g = g0; g < ngroups; g += gstride) {
        int e0 = g * 4;

        // commit prefetched rows to smem (transposed)
        #pragma unroll
        for (int ee = 0; ee < 4; ee++) {
            sEA[w][lane][ee]      = pa0[ee];
            sEA[w][lane + 32][ee] = pa1[ee];
        }
        __syncwarp();

        // prefetch NEXT group's edge_attr (covered by GEMV below)
        int gn = g + gstride;
        if (gn < ngroups) {
            #pragma unroll
            for (int ee = 0; ee < 4; ee++) {
                int e = gn * 4 + ee;
                pa0[ee] = (e < E) ? edge_attr[(size_t)e * RR + lane] : 0.f;
                pa1[ee] = (e < E) ? edge_attr[(size_t)e * RR + lane + 32] : 0.f;
            }
        }

        // hoist this group's per-edge loads (latency covered by GEMV)
        float d4[4], vx4[4], vy4[4], vz4[4], zs4[4], zd4[4];
        int di4[4];
        #pragma unroll
        for (int ee = 0; ee < 4; ee++) {
            int e = e0 + ee;
            int ec = (e < E) ? e : (E - 1);
            d4[ee]  = bond_dist[ec];
            vx4[ee] = bond_vec[(size_t)ec * 3 + 0];
            vy4[ee] = bond_vec[(size_t)ec * 3 + 1];
            vz4[ee] = bond_vec[(size_t)ec * 3 + 2];
            int sidx = src[ec];
            di4[ee] = dst[ec];
            zs4[ee] = g_zws[(size_t)sidx * U + lane];
            zd4[ee] = g_zwd[(size_t)di4[ee] * U + lane];
        }

        unsigned long long w1a = pk2(b1, b1), w1b = pk2(b1, b1);
        unsigned long long w2a = pk2(b2, b2), w2b = pk2(b2, b2);
        unsigned long long w3a = pk2(b3, b3), w3b = pk2(b3, b3);
        unsigned long long efa = pk2(be3, be3), efb = pk2(be3, be3);

        #pragma unroll 8
        for (int r = 0; r < RR; r++) {
            float c1 = sW1[r * U + lane];
            float c2 = sW2[r * U + lane];
            float c3 = sW3[r * U + lane];
            float ce = sWe3[r * U + lane];
            unsigned long long a01 = *(const unsigned long long*)&sEA[w][r][0];
            unsigned long long a23 = *(const unsigned long long*)&sEA[w][r][2];
            unsigned long long p1 = pk2(c1, c1);
            unsigned long long p2 = pk2(c2, c2);
            unsigned long long p3 = pk2(c3, c3);
            unsigned long long pe = pk2(ce, ce);
            w1a = fma2(a01, p1, w1a);  w1b = fma2(a23, p1, w1b);
            w2a = fma2(a01, p2, w2a);  w2b = fma2(a23, p2, w2b);
            w3a = fma2(a01, p3, w3a);  w3b = fma2(a23, p3, w3b);
            efa = fma2(a01, pe, efa);  efb = fma2(a23, pe, efb);
        }

        float w1[4], w2[4], w3[4], ef[4];
        upk2(w1a, w1[0], w1[1]); upk2(w1b, w1[2], w1[3]);
        upk2(w2a, w2[0], w2[1]); upk2(w2b, w2[2], w2[3]);
        upk2(w3a, w3[0], w3[1]); upk2(w3b, w3[2], w3[3]);
        upk2(efa, ef[0], ef[1]); upk2(efb, ef[2], ef[3]);

        #pragma unroll
        for (int ee = 0; ee < 4; ee++) {
            int e = e0 + ee;
            if (e >= E) break;

            edge_feat_out[(size_t)e * U + lane] = ef[ee];

            float d = d4[ee];
            float C = (d <= 5.0f) ? 0.5f * (__cosf(0.6283185307179586f * d) + 1.0f) : 0.0f;

            float zij = zs4[ee] + zd4[ee] + be2;
            float fI = zij * w1[ee] * C;
            float fA = zij * w2[ee] * C;
            float fS = zij * w3[ee] * C;

            float vx = vx4[ee], vy = vy4[ee], vz = vz4[ee];
            float rn = rsqrtf(vx * vx + vy * vy + vz * vz);
            vx *= rn; vy *= rn; vz *= rn;

            const float third = 1.0f / 3.0f;
            float* acc = g_acc + (size_t)di4[ee] * 384 + lane * 12;
            float s0 = fI,               s1 = fA * vx;
            float s2 = fA * vy,          s3 = fA * vz;
            float s4 = fS * (vx * vx - third), s5 = fS * vx * vy;
            float s6 = fS * vx * vz,     s7 = fS * (vy * vy - third);
            float s8 = fS * vy * vz,     s9 = fS * (vz * vz - third);
            asm volatile("red.global.add.v4.f32 [%0], {%1,%2,%3,%4};"
                         :: "l"(acc), "f"(s0), "f"(s1), "f"(s2), "f"(s3) : "memory");
            asm volatile("red.global.add.v4.f32 [%0], {%1,%2,%3,%4};"
                         :: "l"(acc + 4), "f"(s4), "f"(s5), "f"(s6), "f"(s7) : "memory");
            asm volatile("red.global.add.v2.f32 [%0], {%1,%2};"
                         :: "l"(acc + 8), "f"(s8), "f"(s9) : "memory");
        }
        __syncwarp();   // sEA reuse guard
    }
}

// ---------------------------------------------------------------------------
// Kernel 3: node stage. One warp per node.
// ---------------------------------------------------------------------------
__device__ __forceinline__ float warp_sum(float x) {
    #pragma unroll
    for (int o = 16; o > 0; o >>= 1) x += __shfl_xor_sync(0xffffffffu, x, o);
    return x;
}

__global__ __launch_bounds__(256) void node_kernel(
    const float* __restrict__ Wt0, const float* __restrict__ Wt1,
    const float* __restrict__ Wt2,
    const float* __restrict__ Ws1, const float* __restrict__ bs1,
    const float* __restrict__ Ws2, const float* __restrict__ bs2,
    const float* __restrict__ ln_g, const float* __restrict__ ln_b,
    float* __restrict__ Xout, int N)
{
    __shared__ float sAcc[8][320];
    __shared__ float sNrm[8][32];
    __shared__ float sH1[8][64];
    __shared__ float sH2[8][96];
    __shared__ float sOut[8][288];

    int t = threadIdx.x, lane = t & 31, w = t >> 5;
    int n = blockIdx.x * 8 + w;
    if (n >= N) return;

    const float* acc = g_acc + (size_t)n * 384 + lane * 12;
    float4 ga = *(const float4*)(acc);
    float4 gb = *(const float4*)(acc + 4);
    float2 gc = *(const float2*)(acc + 8);
    float g[10] = {ga.x, ga.y, ga.z, ga.w, gb.x, gb.y, gb.z, gb.w, gc.x, gc.y};
    #pragma unroll
    for (int c = 0; c < 10; c++) sAcc[w][c * 32 + lane] = g[c];

    float nrm = 3.0f * g[0] * g[0]
              + 2.0f * (g[1] * g[1] + g[2] * g[2] + g[3] * g[3])
              + g[4] * g[4] + g[7] * g[7] + g[9] * g[9]
              + 2.0f * (g[5] * g[5] + g[6] * g[6] + g[8] * g[8]);

    float mu = warp_sum(nrm) * (1.0f / 32.0f);
    float dv = nrm - mu;
    float var = warp_sum(dv * dv) * (1.0f / 32.0f);
    float nh = dv * rsqrtf(var + 1e-5f) * ln_g[lane] + ln_b[lane];
    sNrm[w][lane] = nh;
    __syncwarp();

    #pragma unroll
    for (int jj = 0; jj < 2; jj++) {
        int j = lane + jj * 32;
        float h = bs1[j];
        #pragma unroll
        for (int u = 0; u < 32; u++) h = fmaf(sNrm[w][u], Ws1[u * 64 + j], h);
        sH1[w][j] = h / (1.0f + expf(-h));
    }
    __syncwarp();

    #pragma unroll
    for (int kk = 0; kk < 3; kk++) {
        int k2 = lane + kk * 32;
        float h = bs2[k2];
        #pragma unroll
        for (int j = 0; j < 64; j++) h = fmaf(sH1[w][j], Ws2[j * 96 + k2], h);
        sH2[w][k2] = h / (1.0f + expf(-h));
    }
    __syncwarp();

    int v = lane;
    float m[10];
    #pragma unroll
    for (int c = 0; c < 10; c++) m[c] = 0.0f;
    #pragma unroll 8
    for (int u = 0; u < 32; u++) {
        float t0 = Wt0[u * 32 + v], t1 = Wt1[u * 32 + v], t2 = Wt2[u * 32 + v];
        m[0] = fmaf(sAcc[w][0 * 32 + u], t0, m[0]);
        #pragma unroll
        for (int c = 1; c < 4; c++)  m[c] = fmaf(sAcc[w][c * 32 + u], t1, m[c]);
        #pragma unroll
        for (int c = 4; c < 10; c++) m[c] = fmaf(sAcc[w][c * 32 + u], t2, m[c]);
    }

    float c0 = sH2[w][v * 3 + 0];
    float c1 = sH2[w][v * 3 + 1];
    float c2 = sH2[w][v * 3 + 2];

    float* o = &sOut[w][v * 9];
    o[0] =  c0 * m[0] + c2 * m[4];
    o[1] = -c1 * m[3] + c2 * m[5];
    o[2] =  c1 * m[2] + c2 * m[6];
    o[3] =  c1 * m[3] + c2 * m[5];
    o[4] =  c0 * m[0] + c2 * m[7];
    o[5] = -c1 * m[1] + c2 * m[8];
    o[6] = -c1 * m[2] + c2 * m[6];
    o[7] =  c1 * m[1] + c2 * m[8];
    o[8] =  c0 * m[0] + c2 * m[9];
    __syncwarp();

    float* xb = Xout + (size_t)n * 288;
    #pragma unroll
    for (int i = 0; i < 9; i++) xb[lane + i * 32] = sOut[w][lane + i * 32];
}

// ---------------------------------------------------------------------------
extern "C" void kernel_launch(void* const* d_in, const int* in_sizes, int n_in,
                              void* d_out, int out_size) {
    const int*   node_type = (const int*)d_in[0];
    const float* edge_attr = (const float*)d_in[1];
    const float* bond_dist = (const float*)d_in[2];
    const float* bond_vec  = (const float*)d_in[3];
    const int*   src       = (const int*)d_in[4];
    const int*   dst       = (const int*)d_in[5];
    const float* emb_table = (const float*)d_in[6];
    const float* Wd1 = (const float*)d_in[7];  const float* bd1 = (const float*)d_in[8];
    const float* Wd2 = (const float*)d_in[9];  const float* bd2 = (const float*)d_in[10];
    const float* Wd3 = (const float*)d_in[11]; const float* bd3 = (const float*)d_in[12];
    const float* Wemb2 = (const float*)d_in[13]; const float* bemb2 = (const float*)d_in[14];
    const float* Wemb3 = (const float*)d_in[15]; const float* bemb3 = (const float*)d_in[16];
    const float* Wt0 = (const float*)d_in[17];
    const float* Wt1 = (const float*)d_in[18];
    const float* Wt2 = (const float*)d_in[19];
    const float* Ws1 = (const float*)d_in[20]; const float* bs1 = (const float*)d_in[21];
    const float* Ws2 = (const float*)d_in[22]; const float* bs2 = (const float*)d_in[23];
    const float* ln_g = (const float*)d_in[24];
    const float* ln_b = (const float*)d_in[25];

    int N = in_sizes[0];
    int E = in_sizes[4];

    float* out = (float*)d_out;
    float* Xout = out;                          // [N,U,3,3]
    float* ef_out = out + (size_t)N * 288;      // [E,U]

    prep_kernel<<<(N + 7) / 8, 256>>>(node_type, emb_table, Wemb2, N);
    edge_kernel<<<1480, 256>>>(edge_attr, bond_dist, bond_vec, src, dst,
                               Wd1, bd1, Wd2, bd2, Wd3, bd3,
                               bemb2, Wemb3, bemb3,
                               ef_out, E);
    node_kernel<<<(N + 7) / 8, 256>>>(Wt0, Wt1, Wt2, Ws1, bs1, Ws2, bs2,
                                      ln_g, ln_b, Xout, N);
}

// round 10
// speedup vs baseline: 1.1204x; 1.1204x over previous
#include <cuda_runtime.h>
#include <math.h>

#define NMAX 20000
#define U 32
#define RR 64

// Scratch (allocation-free rule: __device__ globals)
__device__ float g_acc[(size_t)NMAX * 320];   // [N][10 comps][32 ch] — coalesced atomics
__device__ float g_zws[(size_t)NMAX * U];     // Z[n] @ Wemb2[:32,:]
__device__ float g_zwd[(size_t)NMAX * U];     // Z[n] @ Wemb2[32:,:]

// ---- packed fp32x2 helpers (Blackwell FFMA2) -------------------------------
__device__ __forceinline__ unsigned long long pk2(float x, float y) {
    unsigned long long r;
    asm("mov.b64 %0, {%1, %2};" : "=l"(r) : "f"(x), "f"(y));
    return r;
}
__device__ __forceinline__ unsigned long long fma2(unsigned long long a,
                                                   unsigned long long b,
                                                   unsigned long long c) {
    unsigned long long d;
    asm("fma.rn.f32x2 %0, %1, %2, %3;" : "=l"(d) : "l"(a), "l"(b), "l"(c));
    return d;
}
__device__ __forceinline__ void upk2(unsigned long long v, float& x, float& y) {
    asm("mov.b64 {%0, %1}, %2;" : "=f"(x), "=f"(y) : "l"(v));
}

// ---------------------------------------------------------------------------
// Kernel 1: zero accumulator (flat float4) + precompute ZWs/ZWd per node.
// ---------------------------------------------------------------------------
__global__ __launch_bounds__(256) void prep_kernel(
    const int* __restrict__ node_type,
    const float* __restrict__ emb_table,
    const float* __restrict__ Wemb2, int N)
{
    int t = threadIdx.x, lane = t & 31, w = t >> 5;
    int idx = blockIdx.x * 256 + t;
    int stride = gridDim.x * 256;

    float4* accv = (float4*)g_acc;
    int tot4 = N * 80;
    float4 z4 = make_float4(0.f, 0.f, 0.f, 0.f);
    for (int i = idx; i < tot4; i += stride) accv[i] = z4;

    int n = blockIdx.x * 8 + w;
    if (n >= N) return;

    float z = emb_table[node_type[n] * U + lane];
    float zs = 0.0f, zd = 0.0f;
    #pragma unroll
    for (int k = 0; k < 32; k++) {
        float zk = __shfl_sync(0xffffffffu, z, k);
        zs = fmaf(zk, Wemb2[k * U + lane], zs);
        zd = fmaf(zk, Wemb2[(k + 32) * U + lane], zd);
    }
    g_zws[(size_t)n * U + lane] = zs;
    g_zwd[(size_t)n * U + lane] = zd;
}

// ---------------------------------------------------------------------------
// Kernel 2: fused edge stage. One warp per 4 edges, FFMA2 GEMV,
// software-pipelined edge_attr staging + hoisted indirect loads,
// coalesced scalar atomic scatter ([comp][lane] layout, 1 line/warp-instr).
// ---------------------------------------------------------------------------
__global__ __launch_bounds__(256) void edge_kernel(
    const float* __restrict__ edge_attr, const float* __restrict__ bond_dist,
    const float* __restrict__ bond_vec, const int* __restrict__ src,
    const int* __restrict__ dst,
    const float* __restrict__ Wd1, const float* __restrict__ bd1,
    const float* __restrict__ Wd2, const float* __restrict__ bd2,
    const float* __restrict__ Wd3, const float* __restrict__ bd3,
    const float* __restrict__ bemb2,
    const float* __restrict__ Wemb3, const float* __restrict__ bemb3,
    float* __restrict__ edge_feat_out, int E)
{
    __shared__ float sW1[RR * U], sW2[RR * U], sW3[RR * U], sWe3[RR * U];
    __shared__ __align__(16) float sEA[8][RR][6];  // [warp][r][edge0..3,pad2]

    int t = threadIdx.x;
    for (int i = t; i < RR * U; i += 256) {
        sW1[i] = Wd1[i]; sW2[i] = Wd2[i]; sW3[i] = Wd3[i]; sWe3[i] = Wemb3[i];
    }
    __syncthreads();

    int lane = t & 31, w = t >> 5;
    float b1 = bd1[lane], b2 = bd2[lane], b3 = bd3[lane];
    float be3 = bemb3[lane], be2 = bemb2[lane];

    int g0 = blockIdx.x * 8 + w;
    int gstride = gridDim.x * 8;
    int ngroups = (E + 3) >> 2;

    // prologue: prefetch first group's edge_attr
    float pa0[4], pa1[4];
    if (g0 < ngroups) {
        #pragma unroll
        for (int ee = 0; ee < 4; ee++) {
            int e = g0 * 4 + ee;
            pa0[ee] = (e < E) ? edge_attr[(size_t)e * RR + lane] : 0.f;
            pa1[ee] = (e < E) ? edge_attr[(size_t)e * RR + lane + 32] : 0.f;
        }
    }

    for (int g = g0; g < ngroups; g += gstride) {
        int e0 = g * 4;

        // commit prefetched rows to smem (transposed)
        #pragma unroll
        for (int ee = 0; ee < 4; ee++) {
            sEA[w][lane][ee]      = pa0[ee];
            sEA[w][lane + 32][ee] = pa1[ee];
        }
        __syncwarp();

        // prefetch NEXT group's edge_attr (latency covered by GEMV below)
        int gn = g + gstride;
        if (gn < ngroups) {
            #pragma unroll
            for (int ee = 0; ee < 4; ee++) {
                int e = gn * 4 + ee;
                pa0[ee] = (e < E) ? edge_attr[(size_t)e * RR + lane] : 0.f;
                pa1[ee] = (e < E) ? edge_attr[(size_t)e * RR + lane + 32] : 0.f;
            }
        }

        // hoist this group's per-edge loads (latency covered by GEMV)
        float d4[4], vx4[4], vy4[4], vz4[4], zs4[4], zd4[4];
        int di4[4];
        #pragma unroll
        for (int ee = 0; ee < 4; ee++) {
            int e = e0 + ee;
            int ec = (e < E) ? e : (E - 1);
            d4[ee]  = bond_dist[ec];
            vx4[ee] = bond_vec[(size_t)ec * 3 + 0];
            vy4[ee] = bond_vec[(size_t)ec * 3 + 1];
            vz4[ee] = bond_vec[(size_t)ec * 3 + 2];
            int sidx = src[ec];
            di4[ee] = dst[ec];
            zs4[ee] = g_zws[(size_t)sidx * U + lane];
            zd4[ee] = g_zwd[(size_t)di4[ee] * U + lane];
        }

        unsigned long long w1a = pk2(b1, b1), w1b = pk2(b1, b1);
        unsigned long long w2a = pk2(b2, b2), w2b = pk2(b2, b2);
        unsigned long long w3a = pk2(b3, b3), w3b = pk2(b3, b3);
        unsigned long long efa = pk2(be3, be3), efb = pk2(be3, be3);

        #pragma unroll 8
        for (int r = 0; r < RR; r++) {
            float c1 = sW1[r * U + lane];
            float c2 = sW2[r * U + lane];
            float c3 = sW3[r * U + lane];
            float ce = sWe3[r * U + lane];
            unsigned long long a01 = *(const unsigned long long*)&sEA[w][r][0];
            unsigned long long a23 = *(const unsigned long long*)&sEA[w][r][2];
            unsigned long long p1 = pk2(c1, c1);
            unsigned long long p2 = pk2(c2, c2);
            unsigned long long p3 = pk2(c3, c3);
            unsigned long long pe = pk2(ce, ce);
            w1a = fma2(a01, p1, w1a);  w1b = fma2(a23, p1, w1b);
            w2a = fma2(a01, p2, w2a);  w2b = fma2(a23, p2, w2b);
            w3a = fma2(a01, p3, w3a);  w3b = fma2(a23, p3, w3b);
            efa = fma2(a01, pe, efa);  efb = fma2(a23, pe, efb);
        }

        float w1[4], w2[4], w3[4], ef[4];
        upk2(w1a, w1[0], w1[1]); upk2(w1b, w1[2], w1[3]);
        upk2(w2a, w2[0], w2[1]); upk2(w2b, w2[2], w2[3]);
        upk2(w3a, w3[0], w3[1]); upk2(w3b, w3[2], w3[3]);
        upk2(efa, ef[0], ef[1]); upk2(efb, ef[2], ef[3]);

        #pragma unroll
        for (int ee = 0; ee < 4; ee++) {
            int e = e0 + ee;
            if (e >= E) break;

            edge_feat_out[(size_t)e * U + lane] = ef[ee];

            float d = d4[ee];
            float C = (d <= 5.0f) ? 0.5f * (__cosf(0.6283185307179586f * d) + 1.0f) : 0.0f;

            float zij = zs4[ee] + zd4[ee] + be2;
            float fI = zij * w1[ee] * C;
            float fA = zij * w2[ee] * C;
            float fS = zij * w3[ee] * C;

            float vx = vx4[ee], vy = vy4[ee], vz = vz4[ee];
            float rn = rsqrtf(vx * vx + vy * vy + vz * vz);
            vx *= rn; vy *= rn; vz *= rn;

            float* acc = g_acc + (size_t)di4[ee] * 320 + lane;
            const float third = 1.0f / 3.0f;
            atomicAdd(acc + 0 * 32, fI);
            atomicAdd(acc + 1 * 32, fA * vx);
            atomicAdd(acc + 2 * 32, fA * vy);
            atomicAdd(acc + 3 * 32, fA * vz);
            atomicAdd(acc + 4 * 32, fS * (vx * vx - third));
            atomicAdd(acc + 5 * 32, fS * vx * vy);
            atomicAdd(acc + 6 * 32, fS * vx * vz);
            atomicAdd(acc + 7 * 32, fS * (vy * vy - third));
            atomicAdd(acc + 8 * 32, fS * vy * vz);
            atomicAdd(acc + 9 * 32, fS * (vz * vz - third));
        }
        __syncwarp();   // sEA reuse guard
    }
}

// ---------------------------------------------------------------------------
// Kernel 3: node stage. One warp per node.
// ---------------------------------------------------------------------------
__device__ __forceinline__ float warp_sum(float x) {
    #pragma unroll
    for (int o = 16; o > 0; o >>= 1) x += __shfl_xor_sync(0xffffffffu, x, o);
    return x;
}

__global__ __launch_bounds__(256) void node_kernel(
    const float* __restrict__ Wt0, const float* __restrict__ Wt1,
    const float* __restrict__ Wt2,
    const float* __restrict__ Ws1, const float* __restrict__ bs1,
    const float* __restrict__ Ws2, const float* __restrict__ bs2,
    const float* __restrict__ ln_g, const float* __restrict__ ln_b,
    float* __restrict__ Xout, int N)
{
    __shared__ float sAcc[8][320];
    __shared__ float sNrm[8][32];
    __shared__ float sH1[8][64];
    __shared__ float sH2[8][96];
    __shared__ float sOut[8][288];

    int t = threadIdx.x, lane = t & 31, w = t >> 5;
    int n = blockIdx.x * 8 + w;
    if (n >= N) return;

    const float* acc = g_acc + (size_t)n * 320;
    float g[10];
    #pragma unroll
    for (int c = 0; c < 10; c++) {
        g[c] = acc[c * 32 + lane];
        sAcc[w][c * 32 + lane] = g[c];
    }
    float nrm = 3.0f * g[0] * g[0]
              + 2.0f * (g[1] * g[1] + g[2] * g[2] + g[3] * g[3])
              + g[4] * g[4] + g[7] * g[7] + g[9] * g[9]
              + 2.0f * (g[5] * g[5] + g[6] * g[6] + g[8] * g[8]);

    float mu = warp_sum(nrm) * (1.0f / 32.0f);
    float dv = nrm - mu;
    float var = warp_sum(dv * dv) * (1.0f / 32.0f);
    float nh = dv * rsqrtf(var + 1e-5f) * ln_g[lane] + ln_b[lane];
    sNrm[w][lane] = nh;
    __syncwarp();

    #pragma unroll
    for (int jj = 0; jj < 2; jj++) {
        int j = lane + jj * 32;
        float h = bs1[j];
        #pragma unroll
        for (int u = 0; u < 32; u++) h = fmaf(sNrm[w][u], Ws1[u * 64 + j], h);
        sH1[w][j] = h / (1.0f + expf(-h));
    }
    __syncwarp();

    #pragma unroll
    for (int kk = 0; kk < 3; kk++) {
        int k2 = lane + kk * 32;
        float h = bs2[k2];
        #pragma unroll
        for (int j = 0; j < 64; j++) h = fmaf(sH1[w][j], Ws2[j * 96 + k2], h);
        sH2[w][k2] = h / (1.0f + expf(-h));
    }
    __syncwarp();

    int v = lane;
    float m[10];
    #pragma unroll
    for (int c = 0; c < 10; c++) m[c] = 0.0f;
    #pragma unroll 8
    for (int u = 0; u < 32; u++) {
        float t0 = Wt0[u * 32 + v], t1 = Wt1[u * 32 + v], t2 = Wt2[u * 32 + v];
        m[0] = fmaf(sAcc[w][0 * 32 + u], t0, m[0]);
        #pragma unroll
        for (int c = 1; c < 4; c++)  m[c] = fmaf(sAcc[w][c * 32 + u], t1, m[c]);
        #pragma unroll
        for (int c = 4; c < 10; c++) m[c] = fmaf(sAcc[w][c * 32 + u], t2, m[c]);
    }

    float c0 = sH2[w][v * 3 + 0];
    float c1 = sH2[w][v * 3 + 1];
    float c2 = sH2[w][v * 3 + 2];

    float* o = &sOut[w][v * 9];
    o[0] =  c0 * m[0] + c2 * m[4];
    o[1] = -c1 * m[3] + c2 * m[5];
    o[2] =  c1 * m[2] + c2 * m[6];
    o[3] =  c1 * m[3] + c2 * m[5];
    o[4] =  c0 * m[0] + c2 * m[7];
    o[5] = -c1 * m[1] + c2 * m[8];
    o[6] = -c1 * m[2] + c2 * m[6];
    o[7] =  c1 * m[1] + c2 * m[8];
    o[8] =  c0 * m[0] + c2 * m[9];
    __syncwarp();

    float* xb = Xout + (size_t)n * 288;
    #pragma unroll
    for (int i = 0; i < 9; i++) xb[lane + i * 32] = sOut[w][lane + i * 32];
}

// ---------------------------------------------------------------------------
extern "C" void kernel_launch(void* const* d_in, const int* in_sizes, int n_in,
                              void* d_out, int out_size) {
    const int*   node_type = (const int*)d_in[0];
    const float* edge_attr = (const float*)d_in[1];
    const float* bond_dist = (const float*)d_in[2];
    const float* bond_vec  = (const float*)d_in[3];
    const int*   src       = (const int*)d_in[4];
    const int*   dst       = (const int*)d_in[5];
    const float* emb_table = (const float*)d_in[6];
    const float* Wd1 = (const float*)d_in[7];  const float* bd1 = (const float*)d_in[8];
    const float* Wd2 = (const float*)d_in[9];  const float* bd2 = (const float*)d_in[10];
    const float* Wd3 = (const float*)d_in[11]; const float* bd3 = (const float*)d_in[12];
    const float* Wemb2 = (const float*)d_in[13]; const float* bemb2 = (const float*)d_in[14];
    const float* Wemb3 = (const float*)d_in[15]; const float* bemb3 = (const float*)d_in[16];
    const float* Wt0 = (const float*)d_in[17];
    const float* Wt1 = (const float*)d_in[18];
    const float* Wt2 = (const float*)d_in[19];
    const float* Ws1 = (const float*)d_in[20]; const float* bs1 = (const float*)d_in[21];
    const float* Ws2 = (const float*)d_in[22]; const float* bs2 = (const float*)d_in[23];
    const float* ln_g = (const float*)d_in[24];
    const float* ln_b = (const float*)d_in[25];

    int N = in_sizes[0];
    int E = in_sizes[4];

    float* out = (float*)d_out;
    float* Xout = out;                          // [N,U,3,3]
    float* ef_out = out + (size_t)N * 288;      // [E,U]

    prep_kernel<<<(N + 7) / 8, 256>>>(node_type, emb_table, Wemb2, N);
    edge_kernel<<<1480, 256>>>(edge_attr, bond_dist, bond_vec, src, dst,
                               Wd1, bd1, Wd2, bd2, Wd3, bd3,
                               bemb2, Wemb3, bemb3,
                               ef_out, E);
    node_kernel<<<(N + 7) / 8, 256>>>(Wt0, Wt1, Wt2, Ws1, bs1, Ws2, bs2,
                                      ln_g, ln_b, Xout, N);
}

// round 11
// speedup vs baseline: 1.2333x; 1.1008x over previous
#include <cuda_runtime.h>
#include <math.h>

#define NMAX 20000
#define U 32
#define RR 64

// Scratch (allocation-free rule: __device__ globals)
__device__ float g_acc[(size_t)NMAX * 320];   // [N][10 comps][32 ch] — coalesced atomics
__device__ float g_zws[(size_t)NMAX * U];     // Z[n] @ Wemb2[:32,:]
__device__ float g_zwd[(size_t)NMAX * U];     // Z[n] @ Wemb2[32:,:]

// ---- packed fp32x2 helpers (Blackwell FFMA2) -------------------------------
__device__ __forceinline__ unsigned long long pk2(float x, float y) {
    unsigned long long r;
    asm("mov.b64 %0, {%1, %2};" : "=l"(r) : "f"(x), "f"(y));
    return r;
}
__device__ __forceinline__ unsigned long long fma2(unsigned long long a,
                                                   unsigned long long b,
                                                   unsigned long long c) {
    unsigned long long d;
    asm("fma.rn.f32x2 %0, %1, %2, %3;" : "=l"(d) : "l"(a), "l"(b), "l"(c));
    return d;
}
__device__ __forceinline__ void upk2(unsigned long long v, float& x, float& y) {
    asm("mov.b64 {%0, %1}, %2;" : "=f"(x), "=f"(y) : "l"(v));
}

// ---------------------------------------------------------------------------
// Kernel 1: zero accumulator (flat float4) + precompute ZWs/ZWd per node.
// ---------------------------------------------------------------------------
__global__ __launch_bounds__(256) void prep_kernel(
    const int* __restrict__ node_type,
    const float* __restrict__ emb_table,
    const float* __restrict__ Wemb2, int N)
{
    int t = threadIdx.x, lane = t & 31, w = t >> 5;
    int idx = blockIdx.x * 256 + t;
    int stride = gridDim.x * 256;

    float4* accv = (float4*)g_acc;
    int tot4 = N * 80;
    float4 z4 = make_float4(0.f, 0.f, 0.f, 0.f);
    for (int i = idx; i < tot4; i += stride) accv[i] = z4;

    int n = blockIdx.x * 8 + w;
    if (n >= N) return;

    float z = emb_table[node_type[n] * U + lane];
    float zs = 0.0f, zd = 0.0f;
    #pragma unroll
    for (int k = 0; k < 32; k++) {
        float zk = __shfl_sync(0xffffffffu, z, k);
        zs = fmaf(zk, Wemb2[k * U + lane], zs);
        zd = fmaf(zk, Wemb2[(k + 32) * U + lane], zd);
    }
    g_zws[(size_t)n * U + lane] = zs;
    g_zwd[(size_t)n * U + lane] = zd;
}

// ---------------------------------------------------------------------------
// Kernel 2: fused edge stage. One warp per 8 EDGES (weight LDS amortized 8x),
// FFMA2 GEMV over 4 edge-pairs, coalesced scalar atomic scatter.
// ---------------------------------------------------------------------------
#define EPW 8   // edges per warp

__global__ __launch_bounds__(256) void edge_kernel(
    const float* __restrict__ edge_attr, const float* __restrict__ bond_dist,
    const float* __restrict__ bond_vec, const int* __restrict__ src,
    const int* __restrict__ dst,
    const float* __restrict__ Wd1, const float* __restrict__ bd1,
    const float* __restrict__ Wd2, const float* __restrict__ bd2,
    const float* __restrict__ Wd3, const float* __restrict__ bd3,
    const float* __restrict__ bemb2,
    const float* __restrict__ Wemb3, const float* __restrict__ bemb3,
    float* __restrict__ edge_feat_out, int E)
{
    __shared__ float sW1[RR * U], sW2[RR * U], sW3[RR * U], sWe3[RR * U];
    __shared__ __align__(16) float sEA[8][RR][EPW + 2];  // [warp][r][edge0..7,pad2]

    int t = threadIdx.x;
    for (int i = t; i < RR * U; i += 256) {
        sW1[i] = Wd1[i]; sW2[i] = Wd2[i]; sW3[i] = Wd3[i]; sWe3[i] = Wemb3[i];
    }
    __syncthreads();

    int lane = t & 31, w = t >> 5;
    float b1 = bd1[lane], b2 = bd2[lane], b3 = bd3[lane];
    float be3 = bemb3[lane], be2 = bemb2[lane];

    int g0 = blockIdx.x * 8 + w;
    int gstride = gridDim.x * 8;
    int ngroups = (E + EPW - 1) / EPW;

    for (int g = g0; g < ngroups; g += gstride) {
        int e0 = g * EPW;

        // stage 8 edge_attr rows, transposed to [r][ee]
        #pragma unroll
        for (int ee = 0; ee < EPW; ee++) {
            int e = e0 + ee;
            float a0 = 0.f, a1 = 0.f;
            if (e < E) {
                a0 = edge_attr[(size_t)e * RR + lane];
                a1 = edge_attr[(size_t)e * RR + lane + 32];
            }
            sEA[w][lane][ee]      = a0;
            sEA[w][lane + 32][ee] = a1;
        }
        __syncwarp();

        // 4 edge-pairs × 4 output arrays, FFMA2 accumulators
        unsigned long long aw1[4], aw2[4], aw3[4], aef[4];
        #pragma unroll
        for (int p = 0; p < 4; p++) {
            aw1[p] = pk2(b1, b1); aw2[p] = pk2(b2, b2);
            aw3[p] = pk2(b3, b3); aef[p] = pk2(be3, be3);
        }

        #pragma unroll 4
        for (int r = 0; r < RR; r++) {
            unsigned long long p1 = pk2(sW1[r * U + lane], sW1[r * U + lane]);
            unsigned long long p2 = pk2(sW2[r * U + lane], sW2[r * U + lane]);
            unsigned long long p3 = pk2(sW3[r * U + lane], sW3[r * U + lane]);
            unsigned long long pe = pk2(sWe3[r * U + lane], sWe3[r * U + lane]);
            #pragma unroll
            for (int p = 0; p < 4; p++) {
                unsigned long long a = *(const unsigned long long*)&sEA[w][r][p * 2];
                aw1[p] = fma2(a, p1, aw1[p]);
                aw2[p] = fma2(a, p2, aw2[p]);
                aw3[p] = fma2(a, p3, aw3[p]);
                aef[p] = fma2(a, pe, aef[p]);
            }
        }

        float w1[EPW], w2[EPW], w3[EPW], ef[EPW];
        #pragma unroll
        for (int p = 0; p < 4; p++) {
            upk2(aw1[p], w1[p * 2], w1[p * 2 + 1]);
            upk2(aw2[p], w2[p * 2], w2[p * 2 + 1]);
            upk2(aw3[p], w3[p * 2], w3[p * 2 + 1]);
            upk2(aef[p], ef[p * 2], ef[p * 2 + 1]);
        }

        #pragma unroll
        for (int ee = 0; ee < EPW; ee++) {
            int e = e0 + ee;
            if (e >= E) break;

            edge_feat_out[(size_t)e * U + lane] = ef[ee];

            float d = bond_dist[e];
            float C = (d <= 5.0f) ? 0.5f * (__cosf(0.6283185307179586f * d) + 1.0f) : 0.0f;

            int sidx = src[e], didx = dst[e];
            float zij = g_zws[(size_t)sidx * U + lane]
                      + g_zwd[(size_t)didx * U + lane] + be2;

            float fI = zij * w1[ee] * C;
            float fA = zij * w2[ee] * C;
            float fS = zij * w3[ee] * C;

            float vx = bond_vec[(size_t)e * 3 + 0];
            float vy = bond_vec[(size_t)e * 3 + 1];
            float vz = bond_vec[(size_t)e * 3 + 2];
            float rn = rsqrtf(vx * vx + vy * vy + vz * vz);
            vx *= rn; vy *= rn; vz *= rn;

            float* acc = g_acc + (size_t)didx * 320 + lane;
            const float third = 1.0f / 3.0f;
            atomicAdd(acc + 0 * 32, fI);
            atomicAdd(acc + 1 * 32, fA * vx);
            atomicAdd(acc + 2 * 32, fA * vy);
            atomicAdd(acc + 3 * 32, fA * vz);
            atomicAdd(acc + 4 * 32, fS * (vx * vx - third));
            atomicAdd(acc + 5 * 32, fS * vx * vy);
            atomicAdd(acc + 6 * 32, fS * vx * vz);
            atomicAdd(acc + 7 * 32, fS * (vy * vy - third));
            atomicAdd(acc + 8 * 32, fS * vy * vz);
            atomicAdd(acc + 9 * 32, fS * (vz * vz - third));
        }
        __syncwarp();   // sEA reuse guard
    }
}

// ---------------------------------------------------------------------------
// Kernel 3: node stage. One warp per node.
// ---------------------------------------------------------------------------
__device__ __forceinline__ float warp_sum(float x) {
    #pragma unroll
    for (int o = 16; o > 0; o >>= 1) x += __shfl_xor_sync(0xffffffffu, x, o);
    return x;
}

__global__ __launch_bounds__(256) void node_kernel(
    const float* __restrict__ Wt0, const float* __restrict__ Wt1,
    const float* __restrict__ Wt2,
    const float* __restrict__ Ws1, const float* __restrict__ bs1,
    const float* __restrict__ Ws2, const float* __restrict__ bs2,
    const float* __restrict__ ln_g, const float* __restrict__ ln_b,
    float* __restrict__ Xout, int N)
{
    __shared__ float sAcc[8][320];
    __shared__ float sNrm[8][32];
    __shared__ float sH1[8][64];
    __shared__ float sH2[8][96];
    __shared__ float sOut[8][288];

    int t = threadIdx.x, lane = t & 31, w = t >> 5;
    int n = blockIdx.x * 8 + w;
    if (n >= N) return;

    const float* acc = g_acc + (size_t)n * 320;
    float g[10];
    #pragma unroll
    for (int c = 0; c < 10; c++) {
        g[c] = acc[c * 32 + lane];
        sAcc[w][c * 32 + lane] = g[c];
    }
    float nrm = 3.0f * g[0] * g[0]
              + 2.0f * (g[1] * g[1] + g[2] * g[2] + g[3] * g[3])
              + g[4] * g[4] + g[7] * g[7] + g[9] * g[9]
              + 2.0f * (g[5] * g[5] + g[6] * g[6] + g[8] * g[8]);

    float mu = warp_sum(nrm) * (1.0f / 32.0f);
    float dv = nrm - mu;
    float var = warp_sum(dv * dv) * (1.0f / 32.0f);
    float nh = dv * rsqrtf(var + 1e-5f) * ln_g[lane] + ln_b[lane];
    sNrm[w][lane] = nh;
    __syncwarp();

    #pragma unroll
    for (int jj = 0; jj < 2; jj++) {
        int j = lane + jj * 32;
        float h = bs1[j];
        #pragma unroll
        for (int u = 0; u < 32; u++) h = fmaf(sNrm[w][u], Ws1[u * 64 + j], h);
        sH1[w][j] = h / (1.0f + expf(-h));
    }
    __syncwarp();

    #pragma unroll
    for (int kk = 0; kk < 3; kk++) {
        int k2 = lane + kk * 32;
        float h = bs2[k2];
        #pragma unroll
        for (int j = 0; j < 64; j++) h = fmaf(sH1[w][j], Ws2[j * 96 + k2], h);
        sH2[w][k2] = h / (1.0f + expf(-h));
    }
    __syncwarp();

    int v = lane;
    float m[10];
    #pragma unroll
    for (int c = 0; c < 10; c++) m[c] = 0.0f;
    #pragma unroll 8
    for (int u = 0; u < 32; u++) {
        float t0 = Wt0[u * 32 + v], t1 = Wt1[u * 32 + v], t2 = Wt2[u * 32 + v];
        m[0] = fmaf(sAcc[w][0 * 32 + u], t0, m[0]);
        #pragma unroll
        for (int c = 1; c < 4; c++)  m[c] = fmaf(sAcc[w][c * 32 + u], t1, m[c]);
        #pragma unroll
        for (int c = 4; c < 10; c++) m[c] = fmaf(sAcc[w][c * 32 + u], t2, m[c]);
    }

    float c0 = sH2[w][v * 3 + 0];
    float c1 = sH2[w][v * 3 + 1];
    float c2 = sH2[w][v * 3 + 2];

    float* o = &sOut[w][v * 9];
    o[0] =  c0 * m[0] + c2 * m[4];
    o[1] = -c1 * m[3] + c2 * m[5];
    o[2] =  c1 * m[2] + c2 * m[6];
    o[3] =  c1 * m[3] + c2 * m[5];
    o[4] =  c0 * m[0] + c2 * m[7];
    o[5] = -c1 * m[1] + c2 * m[8];
    o[6] = -c1 * m[2] + c2 * m[6];
    o[7] =  c1 * m[1] + c2 * m[8];
    o[8] =  c0 * m[0] + c2 * m[9];
    __syncwarp();

    float* xb = Xout + (size_t)n * 288;
    #pragma unroll
    for (int i = 0; i < 9; i++) xb[lane + i * 32] = sOut[w][lane + i * 32];
}

// ---------------------------------------------------------------------------
extern "C" void kernel_launch(void* const* d_in, const int* in_sizes, int n_in,
                              void* d_out, int out_size) {
    const int*   node_type = (const int*)d_in[0];
    const float* edge_attr = (const float*)d_in[1];
    const float* bond_dist = (const float*)d_in[2];
    const float* bond_vec  = (const float*)d_in[3];
    const int*   src       = (const int*)d_in[4];
    const int*   dst       = (const int*)d_in[5];
    const float* emb_table = (const float*)d_in[6];
    const float* Wd1 = (const float*)d_in[7];  const float* bd1 = (const float*)d_in[8];
    const float* Wd2 = (const float*)d_in[9];  const float* bd2 = (const float*)d_in[10];
    const float* Wd3 = (const float*)d_in[11]; const float* bd3 = (const float*)d_in[12];
    const float* Wemb2 = (const float*)d_in[13]; const float* bemb2 = (const float*)d_in[14];
    const float* Wemb3 = (const float*)d_in[15]; const float* bemb3 = (const float*)d_in[16];
    const float* Wt0 = (const float*)d_in[17];
    const float* Wt1 = (const float*)d_in[18];
    const float* Wt2 = (const float*)d_in[19];
    const float* Ws1 = (const float*)d_in[20]; const float* bs1 = (const float*)d_in[21];
    const float* Ws2 = (const float*)d_in[22]; const float* bs2 = (const float*)d_in[23];
    const float* ln_g = (const float*)d_in[24];
    const float* ln_b = (const float*)d_in[25];

    int N = in_sizes[0];
    int E = in_sizes[4];

    float* out = (float*)d_out;
    float* Xout = out;                          // [N,U,3,3]
    float* ef_out = out + (size_t)N * 288;      // [E,U]

    prep_kernel<<<(N + 7) / 8, 256>>>(node_type, emb_table, Wemb2, N);
    edge_kernel<<<1480, 256>>>(edge_attr, bond_dist, bond_vec, src, dst,
                               Wd1, bd1, Wd2, bd2, Wd3, bd3,
                               bemb2, Wemb3, bemb3,
                               ef_out, E);
    node_kernel<<<(N + 7) / 8, 256>>>(Wt0, Wt1, Wt2, Ws1, bs1, Ws2, bs2,
                                      ln_g, ln_b, Xout, N);
}